// round 9
// baseline (speedup 1.0000x reference)
#include <cuda_runtime.h>
#include <cuda_fp16.h>
#include <cstdint>

#define NTOT   262144
#define NTILES 16384                    // 16 n per tile
#define SCALE  0.14433756729740643f

// smem (from 1KB-aligned base)
#define OFF_A   0                       // 64 rows x 272B fp16: bytes [0,128)=xh(k0..63), [128,256)=xl
#define OFF_XP  17408                   // 64 x 60 f32 (OS aliases)
#define OFF_OS  OFF_XP                  // 16 n x 224 f32 = 14336 <= 15360
#define OFF_T   32768                   // 64 x 60 f32
#define OFF_AP  48128                   // probs: 16 n x 4 s x float4
#define SMEM_USED 49152
#define SMEM_TOTAL (SMEM_USED + 1024)

// B in mma-fragment order: [strip(7)][kstep(8: 4 wh + 4 wl)][lane(32)] -> uint4
__device__ uint4 g_Bfrag[7 * 8 * 32];

__device__ __forceinline__ float foldw(int j, int k,
                                       const float* wq, const float* wk,
                                       const float* wv, const float* wfc) {
    if (k >= 55) return 0.f;
    if (j < 55) {
        float s = 0.f;
        #pragma unroll 8
        for (int e = 0; e < 48; e++) s += wq[e * 55 + k] * wk[e * 55 + j];
        return s * SCALE;
    }
    if (j >= 56 && j < 111) {
        int dd = j - 56;
        float s = 0.f;
        #pragma unroll 8
        for (int e = 0; e < 48; e++) s += wv[e * 55 + k] * wfc[dd * 48 + e];
        return s;
    }
    return 0.f;
}
__device__ __forceinline__ uint32_t pack2(float w0, float w1, bool lo) {
    __half h0 = __float2half_rn(w0), h1 = __float2half_rn(w1);
    __half o0 = lo ? __float2half_rn(w0 - __half2float(h0)) : h0;
    __half o1 = lo ? __float2half_rn(w1 - __half2float(h1)) : h1;
    return (uint32_t)__half_as_ushort(o0) | ((uint32_t)__half_as_ushort(o1) << 16);
}

__global__ void prep_kernel(const float* __restrict__ wq, const float* __restrict__ wk,
                            const float* __restrict__ wv, const float* __restrict__ wfc) {
    int idx = blockIdx.x * 256 + threadIdx.x;
    if (idx >= 1792) return;
    int lane  = idx & 31;
    int ks    = (idx >> 5) & 7;
    int strip = idx >> 8;
    bool lo   = ks >= 4;
    int kb    = (lo ? ks - 4 : ks) * 16 + 2 * (lane & 3);
    int r     = strip * 16 + (lane >> 2);
    uint4 v;
    v.x = pack2(foldw(r,     kb,     wq,wk,wv,wfc), foldw(r,     kb + 1, wq,wk,wv,wfc), lo);
    v.y = pack2(foldw(r,     kb + 8, wq,wk,wv,wfc), foldw(r,     kb + 9, wq,wk,wv,wfc), lo);
    v.z = pack2(foldw(r + 8, kb,     wq,wk,wv,wfc), foldw(r + 8, kb + 1, wq,wk,wv,wfc), lo);
    v.w = pack2(foldw(r + 8, kb + 8, wq,wk,wv,wfc), foldw(r + 8, kb + 9, wq,wk,wv,wfc), lo);
    g_Bfrag[idx] = v;
}

__device__ __forceinline__ uint32_t s2u(const void* p) {
    uint32_t a;
    asm("{ .reg .u64 t; cvta.to.shared.u64 t, %1; cvt.u32.u64 %0, t; }" : "=r"(a) : "l"(p));
    return a;
}
__device__ __forceinline__ void ldsm4(uint32_t* r, uint32_t addr) {
    asm volatile("ldmatrix.sync.aligned.m8n8.x4.shared.b16 {%0,%1,%2,%3}, [%4];"
                 : "=r"(r[0]), "=r"(r[1]), "=r"(r[2]), "=r"(r[3]) : "r"(addr));
}
__device__ __forceinline__ void mma16816(float* c, const uint32_t* a, uint32_t b0, uint32_t b1) {
    asm volatile("mma.sync.aligned.m16n8k16.row.col.f32.f16.f16.f32 "
                 "{%0,%1,%2,%3}, {%4,%5,%6,%7}, {%8,%9}, {%0,%1,%2,%3};"
                 : "+f"(c[0]), "+f"(c[1]), "+f"(c[2]), "+f"(c[3])
                 : "r"(a[0]), "r"(a[1]), "r"(a[2]), "r"(a[3]), "r"(b0), "r"(b1));
}

__global__ __launch_bounds__(128, 4) void mha_kernel(const float* __restrict__ x,
                                                     const float* __restrict__ bfc,
                                                     float* __restrict__ out) {
    extern __shared__ char smraw[];
    uint32_t sb0 = s2u(smraw);
    uint32_t sb  = (sb0 + 1023u) & ~1023u;
    char* sm = smraw + (sb - sb0);

    const int tid  = threadIdx.x;
    const int wid  = tid >> 5;
    const int lane = tid & 31;

    for (int i = tid; i < 17408 / 4; i += 128)     // zero A once (row pads persist)
        *(uint32_t*)(sm + OFF_A + i * 4) = 0u;

    const int gid = lane >> 2, tig = lane & 3;
    const int town = gid & 3;
    const int R0  = wid * 16;
    const uint32_t aBase = sb + OFF_A + (uint32_t)(R0 + (lane & 15)) * 272
                         + (uint32_t)((lane >> 4) & 1) * 16;

    float biasv[14];
    int   posD[14];
    {
        int dcols[14];
        dcols[0] = 2 * tig; dcols[1] = 2 * tig + 1;
        #pragma unroll
        for (int g = 0; g < 3; g++) {
            int base = 8 + 16 * g + 2 * tig;
            dcols[2 + 4 * g] = base;     dcols[3 + 4 * g] = base + 1;
            dcols[4 + 4 * g] = base + 8; dcols[5 + 4 * g] = base + 9;
        }
        #pragma unroll
        for (int u = 0; u < 14; u++) {
            int d = dcols[u];
            biasv[u] = (d < 55) ? bfc[d] : 0.f;
            int dc = (d < 55) ? d : 0;
            posD[u] = (dc / 5) * 10 + (dc % 5);
        }
    }
    const int posS = (town >> 1) * 110 + (town & 1) * 5;

    float* T   = (float*)(sm + OFF_T);
    float* XP  = (float*)(sm + OFF_XP);
    float* OS  = (float*)(sm + OFF_OS);
    float* APs = (float*)(sm + OFF_AP);
    const uint4* gb0 = g_Bfrag + lane;
    __syncthreads();

    for (int t = blockIdx.x; t < NTILES; t += gridDim.x) {
        // ---- scatter: gmem -> A (xh|xl fp16) + XP (f32) ----
        {
            const float4* xin = (const float4*)(x + (size_t)t * 3520);
            #pragma unroll
            for (int i = 0; i < 7; i++) {
                int idx = tid + 128 * i;
                if (idx < 880) {
                    float4 v = xin[idx];
                    float vv[4] = {v.x, v.y, v.z, v.w};
                    int n_l = idx / 55;
                    int l0  = (idx - n_l * 55) * 4;
                    #pragma unroll
                    for (int jj = 0; jj < 4; jj++) {
                        int l  = l0 + jj;
                        int r  = l / 10, cc = l - r * 10;
                        int p1 = r / 11, h = r - p1 * 11;
                        int p2 = cc / 5, w = cc - p2 * 5;
                        int row = n_l * 4 + p1 * 2 + p2;
                        int d   = h * 5 + w;
                        float val = vv[jj];
                        XP[row * 60 + d] = val;
                        __half hh = __float2half_rn(val);
                        __half hl = __float2half_rn(val - __half2float(hh));
                        *(__half*)(sm + OFF_A + row * 272 + d * 2)        = hh;
                        *(__half*)(sm + OFF_A + row * 272 + 128 + d * 2)  = hl;
                    }
                }
            }
            if (tid < 64) XP[tid * 60 + 55] = 0.f;   // re-zero pad col (OS alias)
        }
        __syncthreads();

        // ---- MMA: 7 strips x (4 wh x {xh,xl} + 4 wl x xh); T->smem, U->regs ----
        float Ureg[2][14];
        {
            uint32_t aFh[4][4], aFl[4][4];
            #pragma unroll
            for (int ks = 0; ks < 4; ks++) {
                ldsm4(aFh[ks], aBase + ks * 32);
                ldsm4(aFl[ks], aBase + 128 + ks * 32);
            }
            #pragma unroll
            for (int ntp = 0; ntp < 7; ntp++) {
                float acc[8];
                #pragma unroll
                for (int q = 0; q < 8; q++) acc[q] = 0.f;
                const uint4* gb = gb0 + ntp * 256;
                #pragma unroll
                for (int ks = 0; ks < 4; ks++) {            // wh x (xh + xl)
                    uint4 bf = __ldg(gb + ks * 32);
                    mma16816(acc,     aFh[ks], bf.x, bf.y);
                    mma16816(acc + 4, aFh[ks], bf.z, bf.w);
                    mma16816(acc,     aFl[ks], bf.x, bf.y);
                    mma16816(acc + 4, aFl[ks], bf.z, bf.w);
                }
                #pragma unroll
                for (int ks = 0; ks < 4; ks++) {            // wl x xh
                    uint4 bf = __ldg(gb + (4 + ks) * 32);
                    mma16816(acc,     aFh[ks], bf.x, bf.y);
                    mma16816(acc + 4, aFh[ks], bf.z, bf.w);
                }
                int c0 = ntp * 16 + 2 * tig;
                int r  = R0 + gid;
                if (ntp <= 3) {
                    *(float2*)(T + r * 60 + c0)       = make_float2(acc[0], acc[1]);
                    *(float2*)(T + (r + 8) * 60 + c0) = make_float2(acc[2], acc[3]);
                }
                if (ntp <= 2) {
                    *(float2*)(T + r * 60 + c0 + 8)       = make_float2(acc[4], acc[5]);
                    *(float2*)(T + (r + 8) * 60 + c0 + 8) = make_float2(acc[6], acc[7]);
                }
                if (ntp == 3) {
                    Ureg[0][0] = acc[4]; Ureg[0][1] = acc[5];
                    Ureg[1][0] = acc[6]; Ureg[1][1] = acc[7];
                }
                if (ntp >= 4) {
                    int u0 = 2 + (ntp - 4) * 4;
                    Ureg[0][u0]     = acc[0]; Ureg[0][u0 + 1] = acc[1];
                    Ureg[1][u0]     = acc[2]; Ureg[1][u0 + 1] = acc[3];
                    Ureg[0][u0 + 2] = acc[4]; Ureg[0][u0 + 3] = acc[5];
                    Ureg[1][u0 + 2] = acc[6]; Ureg[1][u0 + 3] = acc[7];
                }
            }
        }
        __syncthreads();

        // ---- stage C: thread=(n, d-block g). Partial dots over 8 d, shfl-tree ----
        {
            int n8 = tid >> 3, g = tid & 7;
            float S16[16];
            #pragma unroll
            for (int v = 0; v < 16; v++) S16[v] = 0.f;
            if (g < 7) {
                int d0 = 8 * g;
                const float* xb = XP + (n8 * 4) * 60 + d0;
                float4 xv[4][2];
                #pragma unroll
                for (int t4 = 0; t4 < 4; t4++) {
                    xv[t4][0] = *(const float4*)(xb + t4 * 60);
                    xv[t4][1] = *(const float4*)(xb + t4 * 60 + 4);
                }
                const float* tb = T + (n8 * 4) * 60 + d0;
                #pragma unroll
                for (int s4 = 0; s4 < 4; s4++) {
                    float4 ta = *(const float4*)(tb + s4 * 60);
                    float4 tc = *(const float4*)(tb + s4 * 60 + 4);
                    #pragma unroll
                    for (int t4 = 0; t4 < 4; t4++) {
                        float4 a = xv[t4][0], b = xv[t4][1];
                        S16[s4 * 4 + t4] =
                            ta.x * a.x + ta.y * a.y + ta.z * a.z + ta.w * a.w +
                            tc.x * b.x + tc.y * b.y + tc.z * b.z + tc.w * b.w;
                    }
                }
            }
            // reduce over g: round xor4, xor2, xor1 (keep-half, constant indices)
            float S8[8];
            #pragma unroll
            for (int j = 0; j < 8; j++) {
                float send = (g & 4) ? S16[j] : S16[j + 8];
                float keep = (g & 4) ? S16[j + 8] : S16[j];
                S8[j] = keep + __shfl_xor_sync(0xffffffffu, send, 4);
            }
            float S4v[4];
            #pragma unroll
            for (int j = 0; j < 4; j++) {
                float send = (g & 2) ? S8[j] : S8[j + 4];
                float keep = (g & 2) ? S8[j + 4] : S8[j];
                S4v[j] = keep + __shfl_xor_sync(0xffffffffu, send, 2);
            }
            float S2v[2];
            #pragma unroll
            for (int j = 0; j < 2; j++) {
                float send = (g & 1) ? S4v[j] : S4v[j + 2];
                float keep = (g & 1) ? S4v[j + 2] : S4v[j];
                S2v[j] = keep + __shfl_xor_sync(0xffffffffu, send, 1);
            }
            // thread g holds S[2g], S[2g+1]; pair (2s,2s+1) assembles row s
            float o0 = __shfl_xor_sync(0xffffffffu, S2v[0], 1);
            float o1 = __shfl_xor_sync(0xffffffffu, S2v[1], 1);
            float t0, t1, t2, t3;
            if ((g & 1) == 0) { t0 = S2v[0]; t1 = S2v[1]; t2 = o0; t3 = o1; }
            else              { t0 = o0;     t1 = o1;     t2 = S2v[0]; t3 = S2v[1]; }
            float m = fmaxf(fmaxf(t0, t1), fmaxf(t2, t3));
            float e0 = __expf(t0 - m), e1 = __expf(t1 - m);
            float e2 = __expf(t2 - m), e3 = __expf(t3 - m);
            float inv = 1.f / (e0 + e1 + e2 + e3);
            if ((g & 1) == 0)
                *(float4*)(APs + (n8 * 4 + (g >> 1)) * 4) =
                    make_float4(e0 * inv, e1 * inv, e2 * inv, e3 * inv);
        }
        __syncthreads();

        // ---- stage D: out = b + p*U via shfl butterfly over t (lane bits 2,3) ----
        #pragma unroll
        for (int rp = 0; rp < 2; rp++) {
            int row = R0 + gid + 8 * rp;
            int nt  = row >> 2;
            int ab  = (nt * 4 + town) * 4;
            float q0 = APs[ab + town];
            float q1 = APs[ab + (town ^ 1)];
            float q2 = APs[ab + (town ^ 2)];
            float q3 = APs[ab + (town ^ 3)];
            float* os = OS + nt * 224 + posS;
            #pragma unroll
            for (int u = 0; u < 14; u++) {
                float own = Ureg[rp][u];
                float ua = __shfl_xor_sync(0xffffffffu, own, 4);
                float ub = __shfl_xor_sync(0xffffffffu, own, 8);
                float uc = __shfl_xor_sync(0xffffffffu, own, 12);
                float o = biasv[u] + q0 * own + q1 * ua + q2 * ub + q3 * uc;
                if (u != 13 || tig != 3)
                    os[posD[u]] = o;
            }
        }
        __syncthreads();

        // ---- coalesced store OS -> gmem ----
        {
            float* gout = out + (size_t)t * 3520;
            #pragma unroll
            for (int i = 0; i < 7; i++) {
                int idx = tid + 128 * i;
                if (idx < 880) {
                    int n = idx / 55, jj = idx - n * 55;
                    *(float4*)(gout + n * 220 + jj * 4) =
                        *(const float4*)(OS + n * 224 + jj * 4);
                }
            }
        }
        __syncthreads();
    }
}

extern "C" void kernel_launch(void* const* d_in, const int* in_sizes, int n_in,
                              void* d_out, int out_size) {
    const float* x   = (const float*)d_in[0];
    const float* wq  = (const float*)d_in[1];
    const float* wk  = (const float*)d_in[2];
    const float* wv  = (const float*)d_in[3];
    const float* wfc = (const float*)d_in[4];
    const float* bfc = (const float*)d_in[5];
    float* out = (float*)d_out;

    int nsm = 148;
    cudaDeviceGetAttribute(&nsm, cudaDevAttrMultiProcessorCount, 0);

    cudaFuncSetAttribute(mha_kernel, cudaFuncAttributeMaxDynamicSharedMemorySize, SMEM_TOTAL);
    prep_kernel<<<7, 256>>>(wq, wk, wv, wfc);
    mha_kernel<<<nsm * 4, 128, SMEM_TOTAL>>>(x, bfc, out);
}

// round 10
// speedup vs baseline: 1.0239x; 1.0239x over previous
#include <cuda_runtime.h>
#include <cuda_fp16.h>
#include <cstdint>

#define NTOT   262144
#define NTILES 16384                    // 16 n per tile
#define SCALE  0.14433756729740643f

// smem (from 1KB-aligned base)
#define OFF_A   0                       // 64 rows x 240B: half2(hh,hl)[d], d<56; d55+pad zero
#define OFF_T   15360                   // 64 x 60 f32
#define OFF_OS  30720                   // 16 n x 224 f32
#define OFF_AP  45056                   // probs 16 n x 4 s x float4
#define SMEM_USED 46080
#define SMEM_TOTAL (SMEM_USED + 1024)

// B fragments: [strip(7)][kk(14: 7 pass1 + 7 pass2)][lane(32)] -> uint4
__device__ uint4 g_Bfrag[7 * 14 * 32];

__device__ __forceinline__ float foldw(int j, int d,
                                       const float* wq, const float* wk,
                                       const float* wv, const float* wfc) {
    if (d >= 55) return 0.f;
    if (j < 55) {
        float s = 0.f;
        #pragma unroll 8
        for (int e = 0; e < 48; e++) s += wq[e * 55 + d] * wk[e * 55 + j];
        return s * SCALE;
    }
    if (j >= 56 && j < 111) {
        int dd = j - 56;
        float s = 0.f;
        #pragma unroll 8
        for (int e = 0; e < 48; e++) s += wv[e * 55 + d] * wfc[dd * 48 + e];
        return s;
    }
    return 0.f;
}

// value at interleaved k-position kappa for pass p
__device__ __forceinline__ __half bval(int j, int kap, int pass,
                                       const float* wq, const float* wk,
                                       const float* wv, const float* wfc) {
    int d = kap >> 1, odd = kap & 1;
    float w = foldw(j, d, wq, wk, wv, wfc);
    __half hh = __float2half_rn(w);
    if (pass == 0) return hh;                       // wh at both kappa parities
    if (odd) return __float2half_rn(0.f);           // pass2 odd = 0
    return __float2half_rn(w - __half2float(hh));   // wl
}
__device__ __forceinline__ uint32_t packk(int j, int kap, int pass,
                                          const float* wq, const float* wk,
                                          const float* wv, const float* wfc) {
    __half a = bval(j, kap, pass, wq, wk, wv, wfc);
    __half b = bval(j, kap + 1, pass, wq, wk, wv, wfc);
    return (uint32_t)__half_as_ushort(a) | ((uint32_t)__half_as_ushort(b) << 16);
}

__global__ void prep_kernel(const float* __restrict__ wq, const float* __restrict__ wk,
                            const float* __restrict__ wv, const float* __restrict__ wfc) {
    int idx = blockIdx.x * 256 + threadIdx.x;
    if (idx >= 7 * 14 * 32) return;
    int lane  = idx & 31;
    int kk    = (idx >> 5) % 14;
    int strip = idx / (32 * 14);
    int pass  = kk / 7;
    int ks    = kk % 7;
    int q  = lane & 3;
    int r  = strip * 16 + (lane >> 2);
    int k0 = ks * 16 + 2 * q;
    uint4 v;
    v.x = packk(r,     k0,     pass, wq, wk, wv, wfc);
    v.y = packk(r,     k0 + 8, pass, wq, wk, wv, wfc);
    v.z = packk(r + 8, k0,     pass, wq, wk, wv, wfc);
    v.w = packk(r + 8, k0 + 8, pass, wq, wk, wv, wfc);
    g_Bfrag[idx] = v;
}

__device__ __forceinline__ uint32_t s2u(const void* p) {
    uint32_t a;
    asm("{ .reg .u64 t; cvta.to.shared.u64 t, %1; cvt.u32.u64 %0, t; }" : "=r"(a) : "l"(p));
    return a;
}
__device__ __forceinline__ void ldsm4(uint32_t* r, uint32_t addr) {
    asm volatile("ldmatrix.sync.aligned.m8n8.x4.shared.b16 {%0,%1,%2,%3}, [%4];"
                 : "=r"(r[0]), "=r"(r[1]), "=r"(r[2]), "=r"(r[3]) : "r"(addr));
}
__device__ __forceinline__ void mma16816(float* c, const uint32_t* a, uint32_t b0, uint32_t b1) {
    asm volatile("mma.sync.aligned.m16n8k16.row.col.f32.f16.f16.f32 "
                 "{%0,%1,%2,%3}, {%4,%5,%6,%7}, {%8,%9}, {%0,%1,%2,%3};"
                 : "+f"(c[0]), "+f"(c[1]), "+f"(c[2]), "+f"(c[3])
                 : "r"(a[0]), "r"(a[1]), "r"(a[2]), "r"(a[3]), "r"(b0), "r"(b1));
}
// unpack half2(hh,hl) -> fp32 x
__device__ __forceinline__ float xval(uint32_t u) {
    __half2 h = *(__half2*)&u;
    return __low2float(h) + __high2float(h);
}

__global__ __launch_bounds__(128, 4) void mha_kernel(const float* __restrict__ x,
                                                     const float* __restrict__ bfc,
                                                     float* __restrict__ out) {
    extern __shared__ char smraw[];
    uint32_t sb0 = s2u(smraw);
    uint32_t sb  = (sb0 + 1023u) & ~1023u;
    char* sm = smraw + (sb - sb0);

    const int tid  = threadIdx.x;
    const int wid  = tid >> 5;
    const int lane = tid & 31;

    for (int i = tid; i < 15360 / 4; i += 128)     // zero A once (d55 + pads persist)
        *(uint32_t*)(sm + OFF_A + i * 4) = 0u;

    const int gid = lane >> 2, tig = lane & 3;
    const int town = gid & 3;
    const int R0  = wid * 16;
    const uint32_t aBase = sb + OFF_A + (uint32_t)(R0 + (lane & 15)) * 240
                         + (uint32_t)((lane >> 4) & 1) * 16;

    float biasv[14];
    int   posD[14];
    {
        int dcols[14];
        dcols[0] = 2 * tig; dcols[1] = 2 * tig + 1;
        #pragma unroll
        for (int g = 0; g < 3; g++) {
            int base = 8 + 16 * g + 2 * tig;
            dcols[2 + 4 * g] = base;     dcols[3 + 4 * g] = base + 1;
            dcols[4 + 4 * g] = base + 8; dcols[5 + 4 * g] = base + 9;
        }
        #pragma unroll
        for (int u = 0; u < 14; u++) {
            int d = dcols[u];
            biasv[u] = (d < 55) ? bfc[d] : 0.f;
            int dc = (d < 55) ? d : 0;
            posD[u] = (dc / 5) * 10 + (dc % 5);
        }
    }
    const int posS = (town >> 1) * 110 + (town & 1) * 5;

    float* T   = (float*)(sm + OFF_T);
    float* OS  = (float*)(sm + OFF_OS);
    float* APs = (float*)(sm + OFF_AP);
    const uint4* gb0 = g_Bfrag + lane;
    __syncthreads();

    for (int t = blockIdx.x; t < NTILES; t += gridDim.x) {
        // ---- scatter: gmem -> A, ONE half2 (hh,hl) store per element ----
        {
            const float4* xin = (const float4*)(x + (size_t)t * 3520);
            #pragma unroll
            for (int i = 0; i < 7; i++) {
                int idx = tid + 128 * i;
                if (idx < 880) {
                    float4 v = xin[idx];
                    float vv[4] = {v.x, v.y, v.z, v.w};
                    int n_l = idx / 55;
                    int l0  = (idx - n_l * 55) * 4;
                    #pragma unroll
                    for (int jj = 0; jj < 4; jj++) {
                        int l  = l0 + jj;
                        int r  = l / 10, cc = l - r * 10;
                        int p1 = r / 11, h = r - p1 * 11;
                        int p2 = cc / 5, w = cc - p2 * 5;
                        int row = n_l * 4 + p1 * 2 + p2;
                        int d   = h * 5 + w;
                        float val = vv[jj];
                        __half hh = __float2half_rn(val);
                        __half hl = __float2half_rn(val - __half2float(hh));
                        *(__half2*)(sm + OFF_A + row * 240 + d * 4) =
                            __halves2half2(hh, hl);
                    }
                }
            }
        }
        __syncthreads();

        // ---- MMA: 7 strips x (7 ksteps pass1 [wh|wh] + 7 pass2 [wl|0]) ----
        float Ureg[2][14];
        {
            uint32_t aF[7][4];
            #pragma unroll
            for (int ks = 0; ks < 7; ks++) ldsm4(aF[ks], aBase + ks * 32);

            #pragma unroll
            for (int ntp = 0; ntp < 7; ntp++) {
                float acc[8];
                #pragma unroll
                for (int q = 0; q < 8; q++) acc[q] = 0.f;
                const uint4* gb = gb0 + ntp * (14 * 32);
                #pragma unroll
                for (int kk = 0; kk < 7; kk++) {            // pass1: (xh+xl)*wh
                    uint4 bf = __ldg(gb + kk * 32);
                    mma16816(acc,     aF[kk], bf.x, bf.y);
                    mma16816(acc + 4, aF[kk], bf.z, bf.w);
                }
                #pragma unroll
                for (int kk = 0; kk < 7; kk++) {            // pass2: xh*wl
                    uint4 bf = __ldg(gb + (7 + kk) * 32);
                    mma16816(acc,     aF[kk], bf.x, bf.y);
                    mma16816(acc + 4, aF[kk], bf.z, bf.w);
                }
                int c0 = ntp * 16 + 2 * tig;
                int r  = R0 + gid;
                if (ntp <= 3) {
                    *(float2*)(T + r * 60 + c0)       = make_float2(acc[0], acc[1]);
                    *(float2*)(T + (r + 8) * 60 + c0) = make_float2(acc[2], acc[3]);
                }
                if (ntp <= 2) {
                    *(float2*)(T + r * 60 + c0 + 8)       = make_float2(acc[4], acc[5]);
                    *(float2*)(T + (r + 8) * 60 + c0 + 8) = make_float2(acc[6], acc[7]);
                }
                if (ntp == 3) {
                    Ureg[0][0] = acc[4]; Ureg[0][1] = acc[5];
                    Ureg[1][0] = acc[6]; Ureg[1][1] = acc[7];
                }
                if (ntp >= 4) {
                    int u0 = 2 + (ntp - 4) * 4;
                    Ureg[0][u0]     = acc[0]; Ureg[0][u0 + 1] = acc[1];
                    Ureg[1][u0]     = acc[2]; Ureg[1][u0 + 1] = acc[3];
                    Ureg[0][u0 + 2] = acc[4]; Ureg[0][u0 + 3] = acc[5];
                    Ureg[1][u0 + 2] = acc[6]; Ureg[1][u0 + 3] = acc[7];
                }
            }
        }
        __syncthreads();

        // ---- stage C: S = T x^T + softmax; x reconstructed from A (hh+hl) ----
        {
            int nl = tid >> 3;
            int s4 = (tid >> 1) & 3;
            int tp = tid & 1;
            const float4* tr = (const float4*)(T + (nl * 4 + s4) * 60);
            const char* xr0 = sm + OFF_A + (nl * 4 + 2 * tp) * 240;
            const char* xr1 = sm + OFF_A + (nl * 4 + 2 * tp + 1) * 240;
            float sv0 = 0.f, sv1 = 0.f;
            #pragma unroll
            for (int i = 0; i < 14; i++) {
                float4 tv = tr[i];
                uint4 ua = *(const uint4*)(xr0 + 16 * i);
                uint4 ub = *(const uint4*)(xr1 + 16 * i);
                sv0 += tv.x * xval(ua.x) + tv.y * xval(ua.y)
                     + tv.z * xval(ua.z) + tv.w * xval(ua.w);
                sv1 += tv.x * xval(ub.x) + tv.y * xval(ub.y)
                     + tv.z * xval(ub.z) + tv.w * xval(ub.w);
            }
            float o0 = __shfl_xor_sync(0xffffffffu, sv0, 1);
            float o1 = __shfl_xor_sync(0xffffffffu, sv1, 1);
            float t0, t1, t2, t3;
            if (tp == 0) { t0 = sv0; t1 = sv1; t2 = o0; t3 = o1; }
            else         { t0 = o0;  t1 = o1;  t2 = sv0; t3 = sv1; }
            float m = fmaxf(fmaxf(t0, t1), fmaxf(t2, t3));
            float e0 = __expf(t0 - m), e1 = __expf(t1 - m);
            float e2 = __expf(t2 - m), e3 = __expf(t3 - m);
            float inv = 1.f / (e0 + e1 + e2 + e3);
            if (tp == 0)
                *(float4*)(APs + (nl * 4 + s4) * 4) =
                    make_float4(e0 * inv, e1 * inv, e2 * inv, e3 * inv);
        }
        __syncthreads();

        // ---- stage D: out = b + p*U via shfl butterfly over t (lane bits 2,3) ----
        #pragma unroll
        for (int rp = 0; rp < 2; rp++) {
            int row = R0 + gid + 8 * rp;
            int nt  = row >> 2;
            int ab  = (nt * 4 + town) * 4;
            float q0 = APs[ab + town];
            float q1 = APs[ab + (town ^ 1)];
            float q2 = APs[ab + (town ^ 2)];
            float q3 = APs[ab + (town ^ 3)];
            float* os = OS + nt * 224 + posS;
            #pragma unroll
            for (int u = 0; u < 14; u++) {
                float own = Ureg[rp][u];
                float ua = __shfl_xor_sync(0xffffffffu, own, 4);
                float ub = __shfl_xor_sync(0xffffffffu, own, 8);
                float uc = __shfl_xor_sync(0xffffffffu, own, 12);
                float o = biasv[u] + q0 * own + q1 * ua + q2 * ub + q3 * uc;
                if (u != 13 || tig != 3)
                    os[posD[u]] = o;
            }
        }
        __syncthreads();

        // ---- coalesced store OS -> gmem ----
        {
            float* gout = out + (size_t)t * 3520;
            #pragma unroll
            for (int i = 0; i < 7; i++) {
                int idx = tid + 128 * i;
                if (idx < 880) {
                    int n = idx / 55, jj = idx - n * 55;
                    *(float4*)(gout + n * 220 + jj * 4) =
                        *(const float4*)(OS + n * 224 + jj * 4);
                }
            }
        }
        __syncthreads();
    }
}

extern "C" void kernel_launch(void* const* d_in, const int* in_sizes, int n_in,
                              void* d_out, int out_size) {
    const float* x   = (const float*)d_in[0];
    const float* wq  = (const float*)d_in[1];
    const float* wk  = (const float*)d_in[2];
    const float* wv  = (const float*)d_in[3];
    const float* wfc = (const float*)d_in[4];
    const float* bfc = (const float*)d_in[5];
    float* out = (float*)d_out;

    int nsm = 148;
    cudaDeviceGetAttribute(&nsm, cudaDevAttrMultiProcessorCount, 0);

    cudaFuncSetAttribute(mha_kernel, cudaFuncAttributeMaxDynamicSharedMemorySize, SMEM_TOTAL);
    prep_kernel<<<(7 * 14 * 32 + 255) / 256, 256>>>(wq, wk, wv, wfc);
    mha_kernel<<<nsm * 4, 128, SMEM_TOTAL>>>(x, bfc, out);
}

// round 11
// speedup vs baseline: 1.0691x; 1.0441x over previous
#include <cuda_runtime.h>
#include <cuda_fp16.h>
#include <cstdint>

#define NTOT   262144
#define NTILES 16384                    // 16 n per tile
#define SCALE  0.14433756729740643f

// smem (from 1KB-aligned base)
#define OFF_A   0                       // 64 rows x 240B: half2(hh,hl)[d], 16B-units XOR-swizzled
#define OFF_T   15360                   // 64 rows x 232B (58-word pitch, conflict-free)
#define OFF_OS  OFF_T                   // out stage aliases T: 16 n x 224 f32 = 14336 <= 14848
#define OFF_AP  30208                   // probs 16 n x 4 s x float4
#define SMEM_USED 31232
#define SMEM_TOTAL (SMEM_USED + 1024)

// B fragments: [strip(7)][kk(14: 7 pass1 + 7 pass2)][lane(32)] -> uint4
__device__ uint4 g_Bfrag[7 * 14 * 32];

__device__ __forceinline__ float foldw(int j, int d,
                                       const float* wq, const float* wk,
                                       const float* wv, const float* wfc) {
    if (d >= 55) return 0.f;
    if (j < 55) {
        float s = 0.f;
        #pragma unroll 8
        for (int e = 0; e < 48; e++) s += wq[e * 55 + d] * wk[e * 55 + j];
        return s * SCALE;
    }
    if (j >= 56 && j < 111) {
        int dd = j - 56;
        float s = 0.f;
        #pragma unroll 8
        for (int e = 0; e < 48; e++) s += wv[e * 55 + d] * wfc[dd * 48 + e];
        return s;
    }
    return 0.f;
}

__device__ __forceinline__ __half bval(int j, int kap, int pass,
                                       const float* wq, const float* wk,
                                       const float* wv, const float* wfc) {
    int d = kap >> 1, odd = kap & 1;
    float w = foldw(j, d, wq, wk, wv, wfc);
    __half hh = __float2half_rn(w);
    if (pass == 0) return hh;
    if (odd) return __float2half_rn(0.f);
    return __float2half_rn(w - __half2float(hh));
}
__device__ __forceinline__ uint32_t packk(int j, int kap, int pass,
                                          const float* wq, const float* wk,
                                          const float* wv, const float* wfc) {
    __half a = bval(j, kap, pass, wq, wk, wv, wfc);
    __half b = bval(j, kap + 1, pass, wq, wk, wv, wfc);
    return (uint32_t)__half_as_ushort(a) | ((uint32_t)__half_as_ushort(b) << 16);
}

__global__ void prep_kernel(const float* __restrict__ wq, const float* __restrict__ wk,
                            const float* __restrict__ wv, const float* __restrict__ wfc) {
    int idx = blockIdx.x * 256 + threadIdx.x;
    if (idx >= 7 * 14 * 32) return;
    int lane  = idx & 31;
    int kk    = (idx >> 5) % 14;
    int strip = idx / (32 * 14);
    int pass  = kk / 7;
    int ks    = kk % 7;
    int q  = lane & 3;
    int r  = strip * 16 + (lane >> 2);
    int k0 = ks * 16 + 2 * q;
    uint4 v;
    v.x = packk(r,     k0,     pass, wq, wk, wv, wfc);
    v.y = packk(r,     k0 + 8, pass, wq, wk, wv, wfc);
    v.z = packk(r + 8, k0,     pass, wq, wk, wv, wfc);
    v.w = packk(r + 8, k0 + 8, pass, wq, wk, wv, wfc);
    g_Bfrag[idx] = v;
}

__device__ __forceinline__ uint32_t s2u(const void* p) {
    uint32_t a;
    asm("{ .reg .u64 t; cvta.to.shared.u64 t, %1; cvt.u32.u64 %0, t; }" : "=r"(a) : "l"(p));
    return a;
}
__device__ __forceinline__ void ldsm4(uint32_t* r, uint32_t addr) {
    asm volatile("ldmatrix.sync.aligned.m8n8.x4.shared.b16 {%0,%1,%2,%3}, [%4];"
                 : "=r"(r[0]), "=r"(r[1]), "=r"(r[2]), "=r"(r[3]) : "r"(addr));
}
__device__ __forceinline__ void mma16816(float* c, const uint32_t* a, uint32_t b0, uint32_t b1) {
    asm volatile("mma.sync.aligned.m16n8k16.row.col.f32.f16.f16.f32 "
                 "{%0,%1,%2,%3}, {%4,%5,%6,%7}, {%8,%9}, {%0,%1,%2,%3};"
                 : "+f"(c[0]), "+f"(c[1]), "+f"(c[2]), "+f"(c[3])
                 : "r"(a[0]), "r"(a[1]), "r"(a[2]), "r"(a[3]), "r"(b0), "r"(b1));
}
__device__ __forceinline__ float xval(uint32_t u) {
    __half2 h = *(__half2*)&u;
    return __low2float(h) + __high2float(h);
}

__global__ __launch_bounds__(128, 4) void mha_kernel(const float* __restrict__ x,
                                                     const float* __restrict__ bfc,
                                                     float* __restrict__ out) {
    extern __shared__ char smraw[];
    uint32_t sb0 = s2u(smraw);
    uint32_t sb  = (sb0 + 1023u) & ~1023u;
    char* sm = smraw + (sb - sb0);

    const int tid  = threadIdx.x;
    const int wid  = tid >> 5;
    const int lane = tid & 31;

    for (int i = tid; i < 15360 / 4; i += 128)     // zero A once (pads persist)
        *(uint32_t*)(sm + OFF_A + i * 4) = 0u;

    const int gid = lane >> 2, tig = lane & 3;
    const int town = gid & 3;
    const int R0  = wid * 16;
    // ldsm base with swizzle folded into hi: hi' = hi ^ ((row>>3)&1)
    const int arow = R0 + (lane & 15);
    const int hiSw = (((lane >> 4) & 1) ^ ((lane >> 3) & 1));
    const uint32_t aBase = sb + OFF_A + (uint32_t)arow * 240 + (uint32_t)hiSw * 16;

    float biasv[14];
    int   posD[14];
    {
        int dcols[14];
        dcols[0] = 2 * tig; dcols[1] = 2 * tig + 1;
        #pragma unroll
        for (int g = 0; g < 3; g++) {
            int base = 8 + 16 * g + 2 * tig;
            dcols[2 + 4 * g] = base;     dcols[3 + 4 * g] = base + 1;
            dcols[4 + 4 * g] = base + 8; dcols[5 + 4 * g] = base + 9;
        }
        #pragma unroll
        for (int u = 0; u < 14; u++) {
            int d = dcols[u];
            biasv[u] = (d < 55) ? bfc[d] : 0.f;
            int dc = (d < 55) ? d : 0;
            posD[u] = (dc / 5) * 10 + (dc % 5);
        }
    }
    const int posS = (town >> 1) * 110 + (town & 1) * 5;

    float* Tf  = (float*)(sm + OFF_T);      // 58-word pitch
    float* OS  = (float*)(sm + OFF_OS);     // aliases T
    float* APs = (float*)(sm + OFF_AP);
    const uint4* gb0 = g_Bfrag + lane;
    __syncthreads();

    for (int t = blockIdx.x; t < NTILES; t += gridDim.x) {
        // ---- scatter: gmem -> A, one half2 (hh,hl) store per element, swizzled ----
        {
            const float4* xin = (const float4*)(x + (size_t)t * 3520);
            #pragma unroll
            for (int i = 0; i < 7; i++) {
                int idx = tid + 128 * i;
                if (idx < 880) {
                    float4 v = xin[idx];
                    float vv[4] = {v.x, v.y, v.z, v.w};
                    int n_l = idx / 55;
                    int l0  = (idx - n_l * 55) * 4;
                    #pragma unroll
                    for (int jj = 0; jj < 4; jj++) {
                        int l  = l0 + jj;
                        int r  = l / 10, cc = l - r * 10;
                        int p1 = r / 11, h = r - p1 * 11;
                        int p2 = cc / 5, w = cc - p2 * 5;
                        int row = n_l * 4 + p1 * 2 + p2;
                        int d   = h * 5 + w;
                        float val = vv[jj];
                        __half hh = __float2half_rn(val);
                        __half hl = __float2half_rn(val - __half2float(hh));
                        int unit = (d >> 2) ^ ((row >> 3) & 1);
                        *(__half2*)(sm + OFF_A + row * 240 + (unit << 4) + (d & 3) * 4) =
                            __halves2half2(hh, hl);
                    }
                }
            }
        }
        __syncthreads();

        // ---- MMA: 7 strips x (7 ksteps pass1 [wh|wh] + 7 pass2 [wl|0]) ----
        float Ureg[2][14];
        {
            uint32_t aF[7][4];
            #pragma unroll
            for (int ks = 0; ks < 7; ks++) ldsm4(aF[ks], aBase + ks * 32);

            #pragma unroll
            for (int ntp = 0; ntp < 7; ntp++) {
                float acc[8];
                #pragma unroll
                for (int q = 0; q < 8; q++) acc[q] = 0.f;
                const uint4* gb = gb0 + ntp * (14 * 32);
                #pragma unroll
                for (int kk = 0; kk < 7; kk++) {            // pass1: (xh+xl)*wh
                    uint4 bf = __ldg(gb + kk * 32);
                    mma16816(acc,     aF[kk], bf.x, bf.y);
                    mma16816(acc + 4, aF[kk], bf.z, bf.w);
                }
                #pragma unroll
                for (int kk = 0; kk < 7; kk++) {            // pass2: xh*wl
                    uint4 bf = __ldg(gb + (7 + kk) * 32);
                    mma16816(acc,     aF[kk], bf.x, bf.y);
                    mma16816(acc + 4, aF[kk], bf.z, bf.w);
                }
                int c0 = ntp * 16 + 2 * tig;
                int r  = R0 + gid;
                if (ntp <= 3) {
                    *(float2*)(Tf + r * 58 + c0)       = make_float2(acc[0], acc[1]);
                    *(float2*)(Tf + (r + 8) * 58 + c0) = make_float2(acc[2], acc[3]);
                }
                if (ntp <= 2) {
                    *(float2*)(Tf + r * 58 + c0 + 8)       = make_float2(acc[4], acc[5]);
                    *(float2*)(Tf + (r + 8) * 58 + c0 + 8) = make_float2(acc[6], acc[7]);
                }
                if (ntp == 3) {
                    Ureg[0][0] = acc[4]; Ureg[0][1] = acc[5];
                    Ureg[1][0] = acc[6]; Ureg[1][1] = acc[7];
                }
                if (ntp >= 4) {
                    int u0 = 2 + (ntp - 4) * 4;
                    Ureg[0][u0]     = acc[0]; Ureg[0][u0 + 1] = acc[1];
                    Ureg[1][u0]     = acc[2]; Ureg[1][u0 + 1] = acc[3];
                    Ureg[0][u0 + 2] = acc[4]; Ureg[0][u0 + 3] = acc[5];
                    Ureg[1][u0 + 2] = acc[6]; Ureg[1][u0 + 3] = acc[7];
                }
            }
        }
        __syncthreads();

        // ---- stage C: S = T x^T + softmax; x from swizzled A (hh+hl), T pitch 58 ----
        {
            int nl = tid >> 3;
            int s4 = (tid >> 1) & 3;
            int tp = tid & 1;
            const char* tr = sm + OFF_T + (nl * 4 + s4) * 232;
            int xr0 = nl * 4 + 2 * tp;
            int sz  = (xr0 >> 3) & 1;                   // same for xr0 and xr0+1
            const char* xa = sm + OFF_A + xr0 * 240;
            const char* xb = xa + 240;
            float sv0 = 0.f, sv1 = 0.f;
            #pragma unroll
            for (int u = 0; u < 14; u++) {
                float2 t0 = *(const float2*)(tr + u * 16);
                float2 t1 = *(const float2*)(tr + u * 16 + 8);
                int po = (u ^ sz) << 4;
                uint4 ua = *(const uint4*)(xa + po);
                uint4 ub = *(const uint4*)(xb + po);
                sv0 += t0.x * xval(ua.x) + t0.y * xval(ua.y)
                     + t1.x * xval(ua.z) + t1.y * xval(ua.w);
                sv1 += t0.x * xval(ub.x) + t0.y * xval(ub.y)
                     + t1.x * xval(ub.z) + t1.y * xval(ub.w);
            }
            float o0 = __shfl_xor_sync(0xffffffffu, sv0, 1);
            float o1 = __shfl_xor_sync(0xffffffffu, sv1, 1);
            float t0, t1, t2, t3;
            if (tp == 0) { t0 = sv0; t1 = sv1; t2 = o0; t3 = o1; }
            else         { t0 = o0;  t1 = o1;  t2 = sv0; t3 = sv1; }
            float m = fmaxf(fmaxf(t0, t1), fmaxf(t2, t3));
            float e0 = __expf(t0 - m), e1 = __expf(t1 - m);
            float e2 = __expf(t2 - m), e3 = __expf(t3 - m);
            float inv = 1.f / (e0 + e1 + e2 + e3);
            if (tp == 0)
                *(float4*)(APs + (nl * 4 + s4) * 4) =
                    make_float4(e0 * inv, e1 * inv, e2 * inv, e3 * inv);
        }
        __syncthreads();

        // ---- stage D: out = b + p*U via shfl butterfly; OS overwrites T region ----
        #pragma unroll
        for (int rp = 0; rp < 2; rp++) {
            int row = R0 + gid + 8 * rp;
            int nt  = row >> 2;
            int ab  = (nt * 4 + town) * 4;
            float q0 = APs[ab + town];
            float q1 = APs[ab + (town ^ 1)];
            float q2 = APs[ab + (town ^ 2)];
            float q3 = APs[ab + (town ^ 3)];
            float* os = OS + nt * 224 + posS;
            #pragma unroll
            for (int u = 0; u < 14; u++) {
                float own = Ureg[rp][u];
                float ua = __shfl_xor_sync(0xffffffffu, own, 4);
                float ub = __shfl_xor_sync(0xffffffffu, own, 8);
                float uc = __shfl_xor_sync(0xffffffffu, own, 12);
                float o = biasv[u] + q0 * own + q1 * ua + q2 * ub + q3 * uc;
                if (u != 13 || tig != 3)
                    os[posD[u]] = o;
            }
        }
        __syncthreads();

        // ---- coalesced store OS -> gmem ----
        {
            float* gout = out + (size_t)t * 3520;
            #pragma unroll
            for (int i = 0; i < 7; i++) {
                int idx = tid + 128 * i;
                if (idx < 880) {
                    int n = idx / 55, jj = idx - n * 55;
                    *(float4*)(gout + n * 220 + jj * 4) =
                        *(const float4*)(OS + n * 224 + jj * 4);
                }
            }
        }
        __syncthreads();
    }
}

extern "C" void kernel_launch(void* const* d_in, const int* in_sizes, int n_in,
                              void* d_out, int out_size) {
    const float* x   = (const float*)d_in[0];
    const float* wq  = (const float*)d_in[1];
    const float* wk  = (const float*)d_in[2];
    const float* wv  = (const float*)d_in[3];
    const float* wfc = (const float*)d_in[4];
    const float* bfc = (const float*)d_in[5];
    float* out = (float*)d_out;

    int nsm = 148;
    cudaDeviceGetAttribute(&nsm, cudaDevAttrMultiProcessorCount, 0);

    cudaFuncSetAttribute(mha_kernel, cudaFuncAttributeMaxDynamicSharedMemorySize, SMEM_TOTAL);
    prep_kernel<<<(7 * 14 * 32 + 255) / 256, 256>>>(wq, wk, wv, wfc);
    mha_kernel<<<nsm * 4, 128, SMEM_TOTAL>>>(x, bfc, out);
}

// round 12
// speedup vs baseline: 1.2009x; 1.1233x over previous
#include <cuda_runtime.h>
#include <cuda_fp16.h>
#include <cstdint>

#define NTOT   262144
#define NTILES 16384                    // 16 n per tile
#define SCALE  0.14433756729740643f

// A row layout (pitch 304B = 19 x 16B units, XOR-1 swizzle on unit index per 8-row group):
//   units 0..6 : xh halves, byte d*2 (d<56; d=55 slot zero)   unit 7..9: zero pad
//   units 10..16: xl halves, byte 160+d*2                      unit 17..18: zero pad
#define OFF_A   0                       // 64 rows x 304B = 19456
#define OFF_T   19456                   // 64 rows x 232B (58-word pitch)
#define OFF_OS  OFF_T                   // out stage aliases T (14336 <= 14848)
#define OFF_AP  34304                   // probs 16 n x 4 s x float4
#define SMEM_USED 35328
#define SMEM_TOTAL (SMEM_USED + 1024)

// B fragments: [strip(7)][ks(8: 4 wh + 4 wl)][lane(32)] -> uint4 (28 KB)
__device__ uint4 g_Bfrag[7 * 8 * 32];

__device__ __forceinline__ float foldw(int j, int d,
                                       const float* wq, const float* wk,
                                       const float* wv, const float* wfc) {
    if (d >= 55) return 0.f;
    if (j < 55) {
        float s = 0.f;
        #pragma unroll 8
        for (int e = 0; e < 48; e++) s += wq[e * 55 + d] * wk[e * 55 + j];
        return s * SCALE;
    }
    if (j >= 56 && j < 111) {
        int dd = j - 56;
        float s = 0.f;
        #pragma unroll 8
        for (int e = 0; e < 48; e++) s += wv[e * 55 + d] * wfc[dd * 48 + e];
        return s;
    }
    return 0.f;
}
__device__ __forceinline__ uint32_t pack2(float w0, float w1, bool lo) {
    __half h0 = __float2half_rn(w0), h1 = __float2half_rn(w1);
    __half o0 = lo ? __float2half_rn(w0 - __half2float(h0)) : h0;
    __half o1 = lo ? __float2half_rn(w1 - __half2float(h1)) : h1;
    return (uint32_t)__half_as_ushort(o0) | ((uint32_t)__half_as_ushort(o1) << 16);
}

__global__ void prep_kernel(const float* __restrict__ wq, const float* __restrict__ wk,
                            const float* __restrict__ wv, const float* __restrict__ wfc) {
    int idx = blockIdx.x * 256 + threadIdx.x;
    if (idx >= 7 * 8 * 32) return;
    int lane  = idx & 31;
    int ks    = (idx >> 5) & 7;
    int strip = idx >> 8;
    bool lo   = ks >= 4;
    int kb    = (lo ? ks - 4 : ks) * 16 + 2 * (lane & 3);
    int r     = strip * 16 + (lane >> 2);
    uint4 v;
    v.x = pack2(foldw(r,     kb,     wq,wk,wv,wfc), foldw(r,     kb + 1, wq,wk,wv,wfc), lo);
    v.y = pack2(foldw(r,     kb + 8, wq,wk,wv,wfc), foldw(r,     kb + 9, wq,wk,wv,wfc), lo);
    v.z = pack2(foldw(r + 8, kb,     wq,wk,wv,wfc), foldw(r + 8, kb + 1, wq,wk,wv,wfc), lo);
    v.w = pack2(foldw(r + 8, kb + 8, wq,wk,wv,wfc), foldw(r + 8, kb + 9, wq,wk,wv,wfc), lo);
    g_Bfrag[idx] = v;
}

__device__ __forceinline__ uint32_t s2u(const void* p) {
    uint32_t a;
    asm("{ .reg .u64 t; cvta.to.shared.u64 t, %1; cvt.u32.u64 %0, t; }" : "=r"(a) : "l"(p));
    return a;
}
__device__ __forceinline__ void ldsm4(uint32_t* r, uint32_t addr) {
    asm volatile("ldmatrix.sync.aligned.m8n8.x4.shared.b16 {%0,%1,%2,%3}, [%4];"
                 : "=r"(r[0]), "=r"(r[1]), "=r"(r[2]), "=r"(r[3]) : "r"(addr));
}
__device__ __forceinline__ void mma16816(float* c, const uint32_t* a, uint32_t b0, uint32_t b1) {
    asm volatile("mma.sync.aligned.m16n8k16.row.col.f32.f16.f16.f32 "
                 "{%0,%1,%2,%3}, {%4,%5,%6,%7}, {%8,%9}, {%0,%1,%2,%3};"
                 : "+f"(c[0]), "+f"(c[1]), "+f"(c[2]), "+f"(c[3])
                 : "r"(a[0]), "r"(a[1]), "r"(a[2]), "r"(a[3]), "r"(b0), "r"(b1));
}
__device__ __forceinline__ float2 h2f2(uint32_t u) {
    return __half22float2(*(__half2*)&u);
}

__global__ __launch_bounds__(128, 4) void mha_kernel(const float* __restrict__ x,
                                                     const float* __restrict__ bfc,
                                                     float* __restrict__ out) {
    extern __shared__ char smraw[];
    uint32_t sb0 = s2u(smraw);
    uint32_t sb  = (sb0 + 1023u) & ~1023u;
    char* sm = smraw + (sb - sb0);

    const int tid  = threadIdx.x;
    const int wid  = tid >> 5;
    const int lane = tid & 31;

    for (int i = tid; i < 19456 / 4; i += 128)     // zero A once (pads persist)
        *(uint32_t*)(sm + OFF_A + i * 4) = 0u;

    const int gid = lane >> 2, tig = lane & 3;
    const int town = gid & 3;
    const int R0  = wid * 16;
    // ldsm bases: physical unit = logical ^ ((row>>3)&1); hi swizzle folds in
    const int arow = R0 + (lane & 15);
    const int hiSw = ((lane >> 4) & 1) ^ ((arow >> 3) & 1);
    const uint32_t aBaseH = sb + OFF_A + (uint32_t)arow * 304 + (uint32_t)hiSw * 16;
    const uint32_t aBaseL = aBaseH + 160;

    float biasv[14];
    int   posD[14];
    {
        int dcols[14];
        dcols[0] = 2 * tig; dcols[1] = 2 * tig + 1;
        #pragma unroll
        for (int g = 0; g < 3; g++) {
            int base = 8 + 16 * g + 2 * tig;
            dcols[2 + 4 * g] = base;     dcols[3 + 4 * g] = base + 1;
            dcols[4 + 4 * g] = base + 8; dcols[5 + 4 * g] = base + 9;
        }
        #pragma unroll
        for (int u = 0; u < 14; u++) {
            int d = dcols[u];
            biasv[u] = (d < 55) ? bfc[d] : 0.f;
            int dc = (d < 55) ? d : 0;
            posD[u] = (dc / 5) * 10 + (dc % 5);
        }
    }
    const int posS = (town >> 1) * 110 + (town & 1) * 5;

    float* Tf  = (float*)(sm + OFF_T);
    float* OS  = (float*)(sm + OFF_OS);
    float* APs = (float*)(sm + OFF_AP);
    const uint4* gb0 = g_Bfrag + lane;
    __syncthreads();

    for (int t = blockIdx.x; t < NTILES; t += gridDim.x) {
        // ---- scatter: gmem -> A, two half stores (xh, xl) per element, swizzled ----
        {
            const float4* xin = (const float4*)(x + (size_t)t * 3520);
            #pragma unroll
            for (int i = 0; i < 7; i++) {
                int idx = tid + 128 * i;
                if (idx < 880) {
                    float4 v = xin[idx];
                    float vv[4] = {v.x, v.y, v.z, v.w};
                    int n_l = idx / 55;
                    int l0  = (idx - n_l * 55) * 4;
                    #pragma unroll
                    for (int jj = 0; jj < 4; jj++) {
                        int l  = l0 + jj;
                        int r  = l / 10, cc = l - r * 10;
                        int p1 = r / 11, h = r - p1 * 11;
                        int p2 = cc / 5, w = cc - p2 * 5;
                        int row = n_l * 4 + p1 * 2 + p2;
                        int d   = h * 5 + w;
                        float val = vv[jj];
                        __half hh = __float2half_rn(val);
                        __half hl = __float2half_rn(val - __half2float(hh));
                        int ph = (((d >> 3) ^ ((row >> 3) & 1)) << 4) + (d & 7) * 2;
                        char* rp = sm + OFF_A + row * 304;
                        *(__half*)(rp + ph)       = hh;
                        *(__half*)(rp + 160 + ph) = hl;
                    }
                }
            }
        }
        __syncthreads();

        // ---- MMA: 7 strips x (4 ks wh x {xh,xl} + 4 ks wl x xh) = 24 mma/strip ----
        float Ureg[2][14];
        {
            uint32_t aFh[4][4], aFl[4][4];
            #pragma unroll
            for (int ks = 0; ks < 4; ks++) {
                ldsm4(aFh[ks], aBaseH + ks * 32);
                ldsm4(aFl[ks], aBaseL + ks * 32);
            }
            #pragma unroll
            for (int ntp = 0; ntp < 7; ntp++) {
                float acc[8];
                #pragma unroll
                for (int q = 0; q < 8; q++) acc[q] = 0.f;
                const uint4* gb = gb0 + ntp * 256;
                #pragma unroll
                for (int ks = 0; ks < 4; ks++) {            // wh x (xh + xl)
                    uint4 bf = __ldg(gb + ks * 32);
                    mma16816(acc,     aFh[ks], bf.x, bf.y);
                    mma16816(acc + 4, aFh[ks], bf.z, bf.w);
                    mma16816(acc,     aFl[ks], bf.x, bf.y);
                    mma16816(acc + 4, aFl[ks], bf.z, bf.w);
                }
                #pragma unroll
                for (int ks = 0; ks < 4; ks++) {            // wl x xh
                    uint4 bf = __ldg(gb + (4 + ks) * 32);
                    mma16816(acc,     aFh[ks], bf.x, bf.y);
                    mma16816(acc + 4, aFh[ks], bf.z, bf.w);
                }
                int c0 = ntp * 16 + 2 * tig;
                int r  = R0 + gid;
                if (ntp <= 3) {
                    *(float2*)(Tf + r * 58 + c0)       = make_float2(acc[0], acc[1]);
                    *(float2*)(Tf + (r + 8) * 58 + c0) = make_float2(acc[2], acc[3]);
                }
                if (ntp <= 2) {
                    *(float2*)(Tf + r * 58 + c0 + 8)       = make_float2(acc[4], acc[5]);
                    *(float2*)(Tf + (r + 8) * 58 + c0 + 8) = make_float2(acc[6], acc[7]);
                }
                if (ntp == 3) {
                    Ureg[0][0] = acc[4]; Ureg[0][1] = acc[5];
                    Ureg[1][0] = acc[6]; Ureg[1][1] = acc[7];
                }
                if (ntp >= 4) {
                    int u0 = 2 + (ntp - 4) * 4;
                    Ureg[0][u0]     = acc[0]; Ureg[0][u0 + 1] = acc[1];
                    Ureg[1][u0]     = acc[2]; Ureg[1][u0 + 1] = acc[3];
                    Ureg[0][u0 + 2] = acc[4]; Ureg[0][u0 + 3] = acc[5];
                    Ureg[1][u0 + 2] = acc[6]; Ureg[1][u0 + 3] = acc[7];
                }
            }
        }
        __syncthreads();

        // ---- stage C: S = T x^T + softmax; x = xh + xl from swizzled A ----
        {
            int nl = tid >> 3;
            int s4 = (tid >> 1) & 3;
            int tp = tid & 1;
            const float* tr = Tf + (nl * 4 + s4) * 58;
            int xr0 = nl * 4 + 2 * tp;
            int sz  = (xr0 >> 3) & 1;                   // same for xr0, xr0+1
            const char* xa = sm + OFF_A + xr0 * 304;
            const char* xb = xa + 304;
            float sv0 = 0.f, sv1 = 0.f;
            #pragma unroll
            for (int u = 0; u < 7; u++) {
                int off = (u ^ sz) << 4;
                uint4 ha = *(const uint4*)(xa + off);
                uint4 la = *(const uint4*)(xa + 160 + off);
                uint4 hb = *(const uint4*)(xb + off);
                uint4 lb = *(const uint4*)(xb + 160 + off);
                #pragma unroll
                for (int m = 0; m < 4; m++) {
                    float2 tv = *(const float2*)(tr + 8 * u + 2 * m);
                    uint32_t hau = (&ha.x)[m], lau = (&la.x)[m];
                    uint32_t hbu = (&hb.x)[m], lbu = (&lb.x)[m];
                    float2 fa = h2f2(hau), ga = h2f2(lau);
                    float2 fb = h2f2(hbu), gb2 = h2f2(lbu);
                    sv0 += tv.x * (fa.x + ga.x) + tv.y * (fa.y + ga.y);
                    sv1 += tv.x * (fb.x + gb2.x) + tv.y * (fb.y + gb2.y);
                }
            }
            float o0 = __shfl_xor_sync(0xffffffffu, sv0, 1);
            float o1 = __shfl_xor_sync(0xffffffffu, sv1, 1);
            float t0, t1, t2, t3;
            if (tp == 0) { t0 = sv0; t1 = sv1; t2 = o0; t3 = o1; }
            else         { t0 = o0;  t1 = o1;  t2 = sv0; t3 = sv1; }
            float m = fmaxf(fmaxf(t0, t1), fmaxf(t2, t3));
            float e0 = __expf(t0 - m), e1 = __expf(t1 - m);
            float e2 = __expf(t2 - m), e3 = __expf(t3 - m);
            float inv = 1.f / (e0 + e1 + e2 + e3);
            if (tp == 0)
                *(float4*)(APs + (nl * 4 + s4) * 4) =
                    make_float4(e0 * inv, e1 * inv, e2 * inv, e3 * inv);
        }
        __syncthreads();

        // ---- stage D: out = b + p*U via shfl butterfly; OS overwrites T ----
        #pragma unroll
        for (int rp = 0; rp < 2; rp++) {
            int row = R0 + gid + 8 * rp;
            int nt  = row >> 2;
            int ab  = (nt * 4 + town) * 4;
            float q0 = APs[ab + town];
            float q1 = APs[ab + (town ^ 1)];
            float q2 = APs[ab + (town ^ 2)];
            float q3 = APs[ab + (town ^ 3)];
            float* os = OS + nt * 224 + posS;
            #pragma unroll
            for (int u = 0; u < 14; u++) {
                float own = Ureg[rp][u];
                float ua = __shfl_xor_sync(0xffffffffu, own, 4);
                float ub = __shfl_xor_sync(0xffffffffu, own, 8);
                float uc = __shfl_xor_sync(0xffffffffu, own, 12);
                float o = biasv[u] + q0 * own + q1 * ua + q2 * ub + q3 * uc;
                if (u != 13 || tig != 3)
                    os[posD[u]] = o;
            }
        }
        __syncthreads();

        // ---- coalesced store OS -> gmem ----
        {
            float* gout = out + (size_t)t * 3520;
            #pragma unroll
            for (int i = 0; i < 7; i++) {
                int idx = tid + 128 * i;
                if (idx < 880) {
                    int n = idx / 55, jj = idx - n * 55;
                    *(float4*)(gout + n * 220 + jj * 4) =
                        *(const float4*)(OS + n * 224 + jj * 4);
                }
            }
        }
        __syncthreads();
    }
}

extern "C" void kernel_launch(void* const* d_in, const int* in_sizes, int n_in,
                              void* d_out, int out_size) {
    const float* x   = (const float*)d_in[0];
    const float* wq  = (const float*)d_in[1];
    const float* wk  = (const float*)d_in[2];
    const float* wv  = (const float*)d_in[3];
    const float* wfc = (const float*)d_in[4];
    const float* bfc = (const float*)d_in[5];
    float* out = (float*)d_out;

    int nsm = 148;
    cudaDeviceGetAttribute(&nsm, cudaDevAttrMultiProcessorCount, 0);

    cudaFuncSetAttribute(mha_kernel, cudaFuncAttributeMaxDynamicSharedMemorySize, SMEM_TOTAL);
    prep_kernel<<<7, 256>>>(wq, wk, wv, wfc);
    mha_kernel<<<nsm * 4, 128, SMEM_TOTAL>>>(x, bfc, out);
}